// round 2
// baseline (speedup 1.0000x reference)
#include <cuda_runtime.h>
#include <cuda_fp16.h>
#include <stdint.h>

#define T_STEPS 1024
#define BATCH   128
#define INDIM   6
#define HDIM    1536
#define OUTDIM  5
#define GATES   (4*HDIM)          // 6144
#define WELEMS  (GATES*HDIM)      // 9437184

#define NCTA     128
#define NC       12               // h-columns per CTA
#define NLOC     48               // gate columns per CTA (4*NC)
#define NTHREADS 256

#define KC       32               // K elements per pipeline stage
#define PITCH    40               // halfs per smem row (80 B, conflict-free)
#define SA_HALFS (128*PITCH)      // 5120 per buffer
#define SB_HALFS (NLOC*PITCH)     // 1920 per buffer
#define SA_BYTES_BUF (SA_HALFS*2) // 10240
#define SB_BYTES_BUF (SB_HALFS*2) // 3840
#define SB_BASE_HALFS (2*SA_HALFS)            // 10240 halfs
#define SMEM_BYTES (2*SA_BYTES_BUF + 2*SB_BYTES_BUF)   // 28160 (aliased by 24576B gates)

// ---------------- device globals (scratch; no allocations allowed) ----------
__device__ __align__(128) __half g_Whh0[WELEMS];
__device__ __align__(128) __half g_Wih1[WELEMS];
__device__ __align__(128) __half g_Whh1[WELEMS];
__device__ __align__(128) __half g_h0[2][BATCH*HDIM];
__device__ __align__(128) __half g_h1[2][BATCH*HDIM];
__device__ __align__(128) float  g_c0[BATCH*HDIM];
__device__ __align__(128) float  g_c1[BATCH*HDIM];
__device__ __align__(128) float  g_h1f[BATCH*HDIM];
__device__ unsigned g_bar;

// ---------------- weight conversion + barrier reset -------------------------
__global__ void convert_kernel(const float* __restrict__ whh0,
                               const float* __restrict__ wih1,
                               const float* __restrict__ whh1) {
    long i = (long)blockIdx.x * blockDim.x + threadIdx.x;
    if (i == 0) g_bar = 0u;
    if (i < (long)WELEMS)            g_Whh0[i]            = __float2half_rn(whh0[i]);
    else if (i < 2L*WELEMS)          g_Wih1[i - WELEMS]   = __float2half_rn(wih1[i - WELEMS]);
    else if (i < 3L*WELEMS)          g_Whh1[i - 2L*WELEMS]= __float2half_rn(whh1[i - 2L*WELEMS]);
}

// ---------------- helpers ----------------------------------------------------
__device__ __forceinline__ void cpa16(uint32_t s, const void* g) {
    asm volatile("cp.async.cg.shared.global [%0], [%1], 16;\n" :: "r"(s), "l"(g) : "memory");
}
__device__ __forceinline__ void cp_commit() { asm volatile("cp.async.commit_group;\n" ::: "memory"); }
__device__ __forceinline__ void cp_wait1()  { asm volatile("cp.async.wait_group 1;\n" ::: "memory"); }

__device__ __forceinline__ void mma16816(float* d, const uint32_t* a, uint32_t b0, uint32_t b1) {
    asm volatile(
        "mma.sync.aligned.m16n8k16.row.col.f32.f16.f16.f32 "
        "{%0,%1,%2,%3}, {%4,%5,%6,%7}, {%8,%9}, {%0,%1,%2,%3};\n"
        : "+f"(d[0]), "+f"(d[1]), "+f"(d[2]), "+f"(d[3])
        : "r"(a[0]), "r"(a[1]), "r"(a[2]), "r"(a[3]), "r"(b0), "r"(b1));
}

__device__ __forceinline__ float sigm(float x) { return 1.0f / (1.0f + __expf(-x)); }

struct ThreadCtx {
    uint32_t dA0, dA1, dB;   // smem byte addresses (buffer 0)
    int gA0, gA1, gB;        // global half-element offsets (k0 added per stage)
    int doB;
    int gid, tig, wm, wn;
};

__device__ __forceinline__ void load_stage(const ThreadCtx& c, const __half* Ag,
                                           const __half* Wg, int buf, int k0) {
    cpa16(c.dA0 + buf*SA_BYTES_BUF, Ag + c.gA0 + k0);
    cpa16(c.dA1 + buf*SA_BYTES_BUF, Ag + c.gA1 + k0);
    if (c.doB) cpa16(c.dB + buf*SB_BYTES_BUF, Wg + c.gB + k0);
}

__device__ __forceinline__ void compute_stage(const ThreadCtx& c, const __half* sAll,
                                              int buf, float acc[2][3][4]) {
    const __half* bA = sAll + buf*SA_HALFS + c.wm*32*PITCH;
    const __half* bB = sAll + SB_BASE_HALFS + buf*SB_HALFS + c.wn*24*PITCH;
#pragma unroll
    for (int k16 = 0; k16 < 2; k16++) {
        int ko = k16*16 + c.tig*2;
        uint32_t ra[2][4];
#pragma unroll
        for (int tm = 0; tm < 2; tm++) {
            const __half* p = bA + (tm*16 + c.gid)*PITCH + ko;
            ra[tm][0] = *(const uint32_t*)(p);
            ra[tm][1] = *(const uint32_t*)(p + 8*PITCH);
            ra[tm][2] = *(const uint32_t*)(p + 8);
            ra[tm][3] = *(const uint32_t*)(p + 8*PITCH + 8);
        }
#pragma unroll
        for (int tn = 0; tn < 3; tn++) {
            const __half* pb = bB + (tn*8 + c.gid)*PITCH + ko;
            uint32_t rb0 = *(const uint32_t*)(pb);
            uint32_t rb1 = *(const uint32_t*)(pb + 8);
#pragma unroll
            for (int tm = 0; tm < 2; tm++) mma16816(acc[tm][tn], ra[tm], rb0, rb1);
        }
    }
}

// 48-stage K loop over K=1536 with 2-stage cp.async double buffering.
__device__ __forceinline__ void gemm_phase(const ThreadCtx& c, const __half* sAll,
                                           const __half* Ag, const __half* Wg,
                                           float acc[2][3][4]) {
    load_stage(c, Ag, Wg, 0, 0);
    cp_commit();
#pragma unroll 1
    for (int kk = 0; kk < HDIM/KC; kk++) {
        int buf = kk & 1;
        if (kk + 1 < HDIM/KC) load_stage(c, Ag, Wg, buf ^ 1, (kk + 1)*KC);
        cp_commit();
        cp_wait1();
        __syncthreads();
        compute_stage(c, sAll, buf, acc);
        __syncthreads();
    }
}

__device__ __forceinline__ void store_gates(const ThreadCtx& c, float* sG,
                                            const float acc[2][3][4]) {
#pragma unroll
    for (int tm = 0; tm < 2; tm++)
#pragma unroll
        for (int tn = 0; tn < 3; tn++) {
            int row = c.wm*32 + tm*16 + c.gid;
            int n   = c.wn*24 + tn*8 + c.tig*2;
            float* p0 = sG + row*NLOC + n;
            p0[0] = acc[tm][tn][0]; p0[1] = acc[tm][tn][1];
            float* p1 = sG + (row + 8)*NLOC + n;
            p1[0] = acc[tm][tn][2]; p1[1] = acc[tm][tn][3];
        }
}

__device__ __forceinline__ void gridbar(unsigned target) {
    __threadfence();
    __syncthreads();
    if (threadIdx.x == 0) {
        atomicAdd(&g_bar, 1u);
        while (*((volatile unsigned*)&g_bar) < target) { __nanosleep(32); }
    }
    __syncthreads();
}

// ---------------- persistent LSTM kernel ------------------------------------
__global__ void __launch_bounds__(NTHREADS, 1)
lstm_kernel(const float* __restrict__ x,
            const float* __restrict__ Wih0,
            const float* __restrict__ bih0, const float* __restrict__ bhh0,
            const float* __restrict__ bih1, const float* __restrict__ bhh1,
            const float* __restrict__ Wlin, const float* __restrict__ blin,
            float* __restrict__ out) {
    __shared__ __align__(128) unsigned char smem[SMEM_BYTES];
    __shared__ float sWx[NLOC*INDIM];
    __shared__ float sb0v[NLOC], sb1v[NLOC];

    const int tid = threadIdx.x;
    const int j0  = blockIdx.x * NC;
    const __half* sAll = (const __half*)smem;
    float* sG = (float*)smem;   // aliases sA/sB; 128*48*4 = 24576 <= 28160

    // --- per-thread GEMM context ---
    ThreadCtx c;
    {
        uint32_t sbase = (uint32_t)__cvta_generic_to_shared(smem);
        int rowA = tid >> 2, qA = tid & 3;
        c.dA0 = sbase + (uint32_t)((rowA*PITCH + qA*8) * 2);
        c.dA1 = c.dA0 + 64*PITCH*2;
        c.gA0 = rowA*HDIM + qA*8;
        c.gA1 = c.gA0 + 64*HDIM;
        int nB = rowA, qB = qA;
        int wrow = (nB/NC)*HDIM + j0 + (nB % NC);
        c.gB  = wrow*HDIM + qB*8;
        c.dB  = sbase + (uint32_t)(SB_BASE_HALFS*2 + (nB*PITCH + qB*8)*2);
        c.doB = (tid < 4*NLOC);
        int lane = tid & 31, warp = tid >> 5;
        c.gid = lane >> 2; c.tig = lane & 3;
        c.wm = warp & 3;   c.wn = warp >> 2;
    }

    // --- constants in smem: x-projection weight slice + fused biases ---
    for (int n = tid; n < NLOC; n += NTHREADS) {
        int grow = (n/NC)*HDIM + j0 + (n % NC);
        sb0v[n] = bih0[grow] + bhh0[grow];
        sb1v[n] = bih1[grow] + bhh1[grow];
#pragma unroll
        for (int k = 0; k < INDIM; k++) sWx[n*INDIM + k] = Wih0[grow*INDIM + k];
    }

    // --- zero initial state (each CTA owns its column slice) ---
    for (int e = tid; e < BATCH*NC; e += NTHREADS) {
        int b = e / NC, j = e % NC;
        int idx = b*HDIM + j0 + j;
        g_h0[0][idx] = __float2half_rn(0.0f);
        g_h1[0][idx] = __float2half_rn(0.0f);
        g_c0[idx] = 0.0f;
        g_c1[idx] = 0.0f;
    }

    unsigned bc = 0;
    gridbar(++bc * NCTA);

#pragma unroll 1
    for (int t = 0; t < T_STEPS; t++) {
        const int p = t & 1;

        // ================= layer 0 =================
        float acc[2][3][4];
#pragma unroll
        for (int a = 0; a < 2; a++)
#pragma unroll
            for (int b = 0; b < 3; b++)
#pragma unroll
                for (int d = 0; d < 4; d++) acc[a][b][d] = 0.0f;

        gemm_phase(c, sAll, g_h0[p], g_Whh0, acc);
        store_gates(c, sG, acc);
        __syncthreads();

        const float* xt = x + (size_t)t * BATCH * INDIM;
#pragma unroll 1
        for (int e = tid; e < BATCH*NC; e += NTHREADS) {
            int b = e / NC, j = e % NC;
            float iv = sG[b*NLOC + j]          + sb0v[j];
            float fv = sG[b*NLOC + NC + j]     + sb0v[NC + j];
            float gv = sG[b*NLOC + 2*NC + j]   + sb0v[2*NC + j];
            float ov = sG[b*NLOC + 3*NC + j]   + sb0v[3*NC + j];
            const float* xr = xt + b*INDIM;
#pragma unroll
            for (int k = 0; k < INDIM; k++) {
                float xv = xr[k];
                iv += xv * sWx[j*INDIM + k];
                fv += xv * sWx[(NC + j)*INDIM + k];
                gv += xv * sWx[(2*NC + j)*INDIM + k];
                ov += xv * sWx[(3*NC + j)*INDIM + k];
            }
            int idx = b*HDIM + j0 + j;
            float cc = g_c0[idx];
            float cn = sigm(fv)*cc + sigm(iv)*tanhf(gv);
            float hn = sigm(ov)*tanhf(cn);
            g_c0[idx] = cn;
            g_h0[p ^ 1][idx] = __float2half_rn(hn);
        }
        gridbar(++bc * NCTA);

        // ================= layer 1 =================
#pragma unroll
        for (int a = 0; a < 2; a++)
#pragma unroll
            for (int b = 0; b < 3; b++)
#pragma unroll
                for (int d = 0; d < 4; d++) acc[a][b][d] = 0.0f;

        gemm_phase(c, sAll, g_h0[p ^ 1], g_Wih1, acc);
        gemm_phase(c, sAll, g_h1[p],     g_Whh1, acc);
        store_gates(c, sG, acc);
        __syncthreads();

#pragma unroll 1
        for (int e = tid; e < BATCH*NC; e += NTHREADS) {
            int b = e / NC, j = e % NC;
            float iv = sG[b*NLOC + j]          + sb1v[j];
            float fv = sG[b*NLOC + NC + j]     + sb1v[NC + j];
            float gv = sG[b*NLOC + 2*NC + j]   + sb1v[2*NC + j];
            float ov = sG[b*NLOC + 3*NC + j]   + sb1v[3*NC + j];
            int idx = b*HDIM + j0 + j;
            float cc = g_c1[idx];
            float cn = sigm(fv)*cc + sigm(iv)*tanhf(gv);
            float hn = sigm(ov)*tanhf(cn);
            g_c1[idx] = cn;
            g_h1[p ^ 1][idx] = __float2half_rn(hn);
            if (t == T_STEPS - 1) g_h1f[idx] = hn;
        }
        gridbar(++bc * NCTA);
    }

    // ================= final linear (CTA 0 only) =================
    if (blockIdx.x == 0) {
#pragma unroll 1
        for (int e = tid; e < BATCH*OUTDIM; e += NTHREADS) {
            int b = e / OUTDIM, o = e % OUTDIM;
            float s = blin[o];
            const float* hr = g_h1f + b*HDIM;
            const float* wr = Wlin + o*HDIM;
#pragma unroll 4
            for (int k = 0; k < HDIM; k++) s += hr[k] * wr[k];
            out[b*OUTDIM + o] = s;
        }
    }
}

// ---------------- launch ------------------------------------------------------
extern "C" void kernel_launch(void* const* d_in, const int* in_sizes, int n_in,
                              void* d_out, int out_size) {
    const float* x    = (const float*)d_in[0];
    const float* Wih0 = (const float*)d_in[1];
    const float* Whh0 = (const float*)d_in[2];
    const float* bih0 = (const float*)d_in[3];
    const float* bhh0 = (const float*)d_in[4];
    const float* Wih1 = (const float*)d_in[5];
    const float* Whh1 = (const float*)d_in[6];
    const float* bih1 = (const float*)d_in[7];
    const float* bhh1 = (const float*)d_in[8];
    const float* Wlin = (const float*)d_in[9];
    const float* blin = (const float*)d_in[10];

    int cblocks = (3*WELEMS + 255) / 256;
    convert_kernel<<<cblocks, 256>>>(Whh0, Wih1, Whh1);
    lstm_kernel<<<NCTA, NTHREADS>>>(x, Wih0, bih0, bhh0, bih1, bhh1, Wlin, blin,
                                    (float*)d_out);
}

// round 5
// speedup vs baseline: 1.6400x; 1.6400x over previous
#include <cuda_runtime.h>
#include <cuda_fp16.h>
#include <stdint.h>

#define T_STEPS 1024
#define BATCH   128
#define INDIM   6
#define HDIM    1536
#define OUTDIM  5
#define WELEMS  (4*HDIM*HDIM)     // 9437184

#define NCTA     128
#define NC       12               // h-columns per CTA
#define NLOC     48               // gate rows per CTA (4*NC)
#define NTHREADS 256

#define KC       64               // halfs per K stage (128 B rows)
#define NCHUNK   (HDIM/KC)        // 24 stages per 1536-K GEMM
#define NSTAGE   4
#define A_BYTES  (128*128)        // 16384
#define B_BYTES  (NLOC*128)       // 6144
#define STAGE_BYTES (A_BYTES + B_BYTES)        // 22528
#define OFF_GATES   (NSTAGE*STAGE_BYTES)       // 90112 (float[128*48] = 24576)
#define OFF_WX      (OFF_GATES + 128*NLOC*4)   // 114688
#define OFF_B0      (OFF_WX + NLOC*INDIM*4)
#define OFF_B1      (OFF_B0 + NLOC*4)
#define SMEM_DYN    (OFF_B1 + NLOC*4 + 256)    // ~116.5 KB

// ---------------- device globals ---------------------------------------------
__device__ __align__(128) __half g_Whh0[WELEMS];
__device__ __align__(128) __half g_Wih1[WELEMS];
__device__ __align__(128) __half g_Whh1[WELEMS];
__device__ __align__(128) __half g_h0[2][BATCH*HDIM];
__device__ __align__(128) __half g_h1[2][BATCH*HDIM];
__device__ __align__(128) float  g_h1f[BATCH*HDIM];
__device__ unsigned g_bar;

// ---------------- weight convert + barrier reset -----------------------------
__global__ void convert_kernel(const float* __restrict__ whh0,
                               const float* __restrict__ wih1,
                               const float* __restrict__ whh1) {
    long i = (long)blockIdx.x * blockDim.x + threadIdx.x;
    if (i == 0) g_bar = 0u;
    if (i < (long)WELEMS)            g_Whh0[i]             = __float2half_rn(whh0[i]);
    else if (i < 2L*WELEMS)          g_Wih1[i - WELEMS]    = __float2half_rn(wih1[i - WELEMS]);
    else if (i < 3L*WELEMS)          g_Whh1[i - 2L*WELEMS] = __float2half_rn(whh1[i - 2L*WELEMS]);
}

// ---------------- PTX helpers -------------------------------------------------
__device__ __forceinline__ void cpa16(uint32_t s, const void* g) {
    asm volatile("cp.async.cg.shared.global [%0], [%1], 16;\n" :: "r"(s), "l"(g) : "memory");
}
__device__ __forceinline__ void cp_commit() { asm volatile("cp.async.commit_group;\n" ::: "memory"); }
__device__ __forceinline__ void cp_wait2()  { asm volatile("cp.async.wait_group %0;\n" :: "n"(NSTAGE-2) : "memory"); }

__device__ __forceinline__ void ldsm_x4(uint32_t* r, uint32_t addr) {
    asm volatile("ldmatrix.sync.aligned.m8n8.x4.shared.b16 {%0,%1,%2,%3}, [%4];\n"
                 : "=r"(r[0]), "=r"(r[1]), "=r"(r[2]), "=r"(r[3]) : "r"(addr));
}
__device__ __forceinline__ void ldsm_x2(uint32_t* r, uint32_t addr) {
    asm volatile("ldmatrix.sync.aligned.m8n8.x2.shared.b16 {%0,%1}, [%2];\n"
                 : "=r"(r[0]), "=r"(r[1]) : "r"(addr));
}
__device__ __forceinline__ void mma16816(float* d, const uint32_t* a, uint32_t b0, uint32_t b1) {
    asm volatile(
        "mma.sync.aligned.m16n8k16.row.col.f32.f16.f16.f32 "
        "{%0,%1,%2,%3}, {%4,%5,%6,%7}, {%8,%9}, {%0,%1,%2,%3};\n"
        : "+f"(d[0]), "+f"(d[1]), "+f"(d[2]), "+f"(d[3])
        : "r"(a[0]), "r"(a[1]), "r"(a[2]), "r"(a[3]), "r"(b0), "r"(b1));
}

__device__ __forceinline__ float sigm(float x)  { return __fdividef(1.0f, 1.0f + __expf(-x)); }
__device__ __forceinline__ float tanh_f(float x){ return __fdividef(2.0f, 1.0f + __expf(-2.0f*x)) - 1.0f; }

// ---------------- per-thread precomputed context ------------------------------
struct Ctx {
    uint32_t offA0, offA1;   // A row-base byte offsets (tm=0,1) within a stage
    uint32_t offB4, offB2;   // B row-base byte offsets (x4 tiles, x2 tile)
    uint32_t cq4[4], cq2[4]; // per-k16 swizzled column offsets
    int gid, tig, wm, wn;
};

__device__ __forceinline__ void load_stage(uint32_t sb, int buf,
                                           const __half* __restrict__ A,
                                           const __half* __restrict__ W,
                                           int j0, int k0, int tid) {
    uint32_t sbuf = sb + (uint32_t)buf * STAGE_BYTES;
#pragma unroll
    for (int it = 0; it < 4; it++) {           // A: 1024 segs / 256 threads
        int seg = tid + it*NTHREADS;
        int r = seg >> 3, s = seg & 7;
        cpa16(sbuf + (uint32_t)(r*128 + ((s ^ (r & 7)) << 4)),
              A + (size_t)r*HDIM + k0 + s*8);
    }
    {                                           // B: 384 segs
        int seg = tid;
        int r = seg >> 3, s = seg & 7;
        int wrow = (r / NC) * HDIM + j0 + (r % NC);
        cpa16(sbuf + A_BYTES + (uint32_t)(r*128 + ((s ^ (r & 7)) << 4)),
              W + (size_t)wrow*HDIM + k0 + s*8);
        seg = tid + NTHREADS;
        if (seg < 384) {
            r = seg >> 3; s = seg & 7;
            wrow = (r / NC) * HDIM + j0 + (r % NC);
            cpa16(sbuf + A_BYTES + (uint32_t)(r*128 + ((s ^ (r & 7)) << 4)),
                  W + (size_t)wrow*HDIM + k0 + s*8);
        }
    }
}

__device__ __forceinline__ void compute_stage(uint32_t sb, int buf, const Ctx& c,
                                              float acc[2][3][4]) {
    uint32_t stage = sb + (uint32_t)buf * STAGE_BYTES;
    uint32_t bstage = stage + A_BYTES;
#pragma unroll
    for (int q = 0; q < 4; q++) {
        uint32_t ra[2][4], rb[4], rb2[2];
        ldsm_x4(ra[0], stage + c.offA0 + c.cq4[q]);
        ldsm_x4(ra[1], stage + c.offA1 + c.cq4[q]);
        ldsm_x4(rb,    bstage + c.offB4 + c.cq4[q]);
        ldsm_x2(rb2,   bstage + c.offB2 + c.cq2[q]);
#pragma unroll
        for (int tm = 0; tm < 2; tm++) {
            mma16816(acc[tm][0], ra[tm], rb[0],  rb[2]);
            mma16816(acc[tm][1], ra[tm], rb[1],  rb[3]);
            mma16816(acc[tm][2], ra[tm], rb2[0], rb2[1]);
        }
    }
}

// multistage pipelined GEMM over npair K-concatenated (A,W) pairs
__device__ __forceinline__ void gemm_multi(uint32_t sb, const Ctx& c, int j0, int tid,
                                           const __half* A0, const __half* W0,
                                           const __half* A1, const __half* W1,
                                           int npair, float acc[2][3][4]) {
    const int total = npair * NCHUNK;
#pragma unroll
    for (int s = 0; s < NSTAGE-1; s++) {
        const __half* A = (s < NCHUNK) ? A0 : A1;
        const __half* W = (s < NCHUNK) ? W0 : W1;
        load_stage(sb, s % NSTAGE, A, W, j0, (s % NCHUNK)*KC, tid);
        cp_commit();
    }
#pragma unroll 1
    for (int s = 0; s < total; s++) {
        cp_wait2();
        __syncthreads();
        int ns = s + NSTAGE - 1;
        if (ns < total) {
            const __half* A = (ns < NCHUNK) ? A0 : A1;
            const __half* W = (ns < NCHUNK) ? W0 : W1;
            load_stage(sb, ns % NSTAGE, A, W, j0, (ns % NCHUNK)*KC, tid);
        }
        cp_commit();
        compute_stage(sb, s % NSTAGE, c, acc);
    }
}

__device__ __forceinline__ void store_gates(float* sG, const Ctx& c,
                                            const float acc[2][3][4]) {
#pragma unroll
    for (int tm = 0; tm < 2; tm++)
#pragma unroll
        for (int tn = 0; tn < 3; tn++) {
            int row = c.wm*32 + tm*16 + c.gid;
            int n   = c.wn*24 + tn*8 + c.tig*2;
            float* p0 = sG + row*NLOC + n;
            p0[0] = acc[tm][tn][0]; p0[1] = acc[tm][tn][1];
            float* p1 = sG + (row + 8)*NLOC + n;
            p1[0] = acc[tm][tn][2]; p1[1] = acc[tm][tn][3];
        }
}

__device__ __forceinline__ void gridbar(unsigned target) {
    __threadfence();
    __syncthreads();
    if (threadIdx.x == 0) {
        atomicAdd(&g_bar, 1u);
        while (*((volatile unsigned*)&g_bar) < target) { __nanosleep(32); }
    }
    __syncthreads();
}

// ---------------- persistent LSTM kernel -------------------------------------
__global__ void __launch_bounds__(NTHREADS, 1)
lstm_kernel(const float* __restrict__ x,
            const float* __restrict__ Wih0,
            const float* __restrict__ bih0, const float* __restrict__ bhh0,
            const float* __restrict__ bih1, const float* __restrict__ bhh1,
            const float* __restrict__ Wlin, const float* __restrict__ blin,
            float* __restrict__ out) {
    extern __shared__ unsigned char dsm[];
    const int tid = threadIdx.x;
    const int j0  = blockIdx.x * NC;
    const uint32_t sb = (uint32_t)__cvta_generic_to_shared(dsm);
    float* sG  = (float*)(dsm + OFF_GATES);
    float* sWx = (float*)(dsm + OFF_WX);
    float* sB0 = (float*)(dsm + OFF_B0);
    float* sB1 = (float*)(dsm + OFF_B1);

    // ---- per-thread fragment addressing context ----
    Ctx c;
    {
        int lane = tid & 31, warp = tid >> 5;
        c.gid = lane >> 2; c.tig = lane & 3;
        c.wm = warp & 3;   c.wn = warp >> 2;
        int r16 = lane & 15, hi = lane >> 4, xv = lane & 7;
        c.offA0 = (uint32_t)((c.wm*32 + r16) * 128);
        c.offA1 = c.offA0 + 16*128;
        c.offB4 = (uint32_t)((c.wn*24 + r16) * 128);
        c.offB2 = (uint32_t)((c.wn*24 + 16 + (lane & 7)) * 128);
        int hi2 = (lane >> 3) & 1;
#pragma unroll
        for (int q = 0; q < 4; q++) {
            c.cq4[q] = (uint32_t)((((2*q + hi)  ^ xv) << 4));
            c.cq2[q] = (uint32_t)((((2*q + hi2) ^ xv) << 4));
        }
    }

    // ---- constants: x-projection slice + fused biases ----
    for (int n = tid; n < NLOC; n += NTHREADS) {
        int grow = (n / NC) * HDIM + j0 + (n % NC);
        sB0[n] = bih0[grow] + bhh0[grow];
        sB1[n] = bih1[grow] + bhh1[grow];
#pragma unroll
        for (int k = 0; k < INDIM; k++) sWx[n*INDIM + k] = Wih0[grow*INDIM + k];
    }

    // ---- zero initial h state (each CTA owns its slice) ----
    for (int e = tid; e < BATCH*NC; e += NTHREADS) {
        int b = e / NC, j = e % NC;
        int idx = b*HDIM + j0 + j;
        g_h0[0][idx] = __float2half_rn(0.0f);
        g_h1[0][idx] = __float2half_rn(0.0f);
    }

    // c-state in registers: thread owns elements e = tid + i*256, i<6
    float cr0[6], cr1[6];
#pragma unroll
    for (int i = 0; i < 6; i++) { cr0[i] = 0.0f; cr1[i] = 0.0f; }

    unsigned bc = 0;
    gridbar(++bc * NCTA);

#pragma unroll 1
    for (int t = 0; t < T_STEPS; t++) {
        const int p = t & 1;

        // ================= layer 0: gates = Whh0 * h0[p] =================
        float acc[2][3][4];
#pragma unroll
        for (int a = 0; a < 2; a++)
#pragma unroll
            for (int b = 0; b < 3; b++)
#pragma unroll
                for (int d = 0; d < 4; d++) acc[a][b][d] = 0.0f;

        gemm_multi(sb, c, j0, tid, g_h0[p], g_Whh0, g_h0[p], g_Whh0, 1, acc);
        store_gates(sG, c, acc);
        __syncthreads();

        {
            const float* xt = x + (size_t)t * BATCH * INDIM;
#pragma unroll
            for (int i = 0; i < 6; i++) {
                int e = tid + i*NTHREADS;
                int b = e / NC, j = e % NC;
                float iv = sG[b*NLOC + j]          + sB0[j];
                float fv = sG[b*NLOC + NC + j]     + sB0[NC + j];
                float gv = sG[b*NLOC + 2*NC + j]   + sB0[2*NC + j];
                float ov = sG[b*NLOC + 3*NC + j]   + sB0[3*NC + j];
                const float* xr = xt + b*INDIM;
#pragma unroll
                for (int k = 0; k < INDIM; k++) {
                    float xk = xr[k];
                    iv += xk * sWx[j*INDIM + k];
                    fv += xk * sWx[(NC + j)*INDIM + k];
                    gv += xk * sWx[(2*NC + j)*INDIM + k];
                    ov += xk * sWx[(3*NC + j)*INDIM + k];
                }
                float cn = sigm(fv)*cr0[i] + sigm(iv)*tanh_f(gv);
                cr0[i] = cn;
                g_h0[p ^ 1][(size_t)b*HDIM + j0 + j] = __float2half_rn(sigm(ov)*tanh_f(cn));
            }
        }
        gridbar(++bc * NCTA);     // h0[p^1] visible chip-wide

        // ===== layer 1: gates = Wih1*h0[p^1] + Whh1*h1[p] (fused K=3072) =====
#pragma unroll
        for (int a = 0; a < 2; a++)
#pragma unroll
            for (int b = 0; b < 3; b++)
#pragma unroll
                for (int d = 0; d < 4; d++) acc[a][b][d] = 0.0f;

        gemm_multi(sb, c, j0, tid, g_h0[p ^ 1], g_Wih1, g_h1[p], g_Whh1, 2, acc);
        store_gates(sG, c, acc);
        __syncthreads();

        {
            const bool last = (t == T_STEPS - 1);
#pragma unroll
            for (int i = 0; i < 6; i++) {
                int e = tid + i*NTHREADS;
                int b = e / NC, j = e % NC;
                float iv = sG[b*NLOC + j]          + sB1[j];
                float fv = sG[b*NLOC + NC + j]     + sB1[NC + j];
                float gv = sG[b*NLOC + 2*NC + j]   + sB1[2*NC + j];
                float ov = sG[b*NLOC + 3*NC + j]   + sB1[3*NC + j];
                float cn = sigm(fv)*cr1[i] + sigm(iv)*tanh_f(gv);
                cr1[i] = cn;
                float hn = sigm(ov)*tanh_f(cn);
                g_h1[p ^ 1][(size_t)b*HDIM + j0 + j] = __float2half_rn(hn);
                if (last) g_h1f[(size_t)b*HDIM + j0 + j] = hn;
            }
        }
        gridbar(++bc * NCTA);     // h1[p^1] visible chip-wide
    }

    // ================= final linear (CTA 0) =================
    if (blockIdx.x == 0) {
#pragma unroll 1
        for (int e = tid; e < BATCH*OUTDIM; e += NTHREADS) {
            int b = e / OUTDIM, o = e % OUTDIM;
            float s = blin[o];
            const float* hr = g_h1f + (size_t)b*HDIM;
            const float* wr = Wlin + (size_t)o*HDIM;
#pragma unroll 4
            for (int k = 0; k < HDIM; k++) s += hr[k] * wr[k];
            out[b*OUTDIM + o] = s;
        }
    }
}

// ---------------- launch ------------------------------------------------------
extern "C" void kernel_launch(void* const* d_in, const int* in_sizes, int n_in,
                              void* d_out, int out_size) {
    const float* x    = (const float*)d_in[0];
    const float* Wih0 = (const float*)d_in[1];
    const float* Whh0 = (const float*)d_in[2];
    const float* bih0 = (const float*)d_in[3];
    const float* bhh0 = (const float*)d_in[4];
    const float* Wih1 = (const float*)d_in[5];
    const float* Whh1 = (const float*)d_in[6];
    const float* bih1 = (const float*)d_in[7];
    const float* bhh1 = (const float*)d_in[8];
    const float* Wlin = (const float*)d_in[9];
    const float* blin = (const float*)d_in[10];

    cudaFuncSetAttribute(lstm_kernel, cudaFuncAttributeMaxDynamicSharedMemorySize, SMEM_DYN);

    int cblocks = (3*WELEMS + 255) / 256;
    convert_kernel<<<cblocks, 256>>>(Whh0, Wih1, Whh1);
    lstm_kernel<<<NCTA, NTHREADS, SMEM_DYN>>>(x, Wih0, bih0, bhh0, bih1, bhh1,
                                              Wlin, blin, (float*)d_out);
}

// round 6
// speedup vs baseline: 1.8369x; 1.1201x over previous
#include <cuda_runtime.h>
#include <cuda_fp16.h>
#include <stdint.h>

#define T_STEPS 1024
#define BATCH   128
#define INDIM   6
#define HDIM    1536
#define OUTDIM  5
#define WELEMS  (4*HDIM*HDIM)     // 9437184

#define NCTA     128
#define NC       12               // h-columns per CTA
#define NLOC     48               // gate rows per CTA (4*NC)
#define NTHREADS 256

#define KC       128              // halfs per K stage (256 B rows = 2 SW128 atoms)
#define RB       256              // row bytes
#define NCHUNK   (HDIM/KC)        // 12 stages per 1536-K GEMM
#define NSTAGE   3
#define A_BYTES  (128*RB)         // 32768
#define B_BYTES  (NLOC*RB)        // 12288
#define STAGE_BYTES (A_BYTES + B_BYTES)        // 45056
#define OFF_GATES   (NSTAGE*STAGE_BYTES)       // 135168 (float[128*48] = 24576)
#define OFF_WX      (OFF_GATES + 128*NLOC*4)   // 159744
#define OFF_B0      (OFF_WX + NLOC*INDIM*4)
#define OFF_B1      (OFF_B0 + NLOC*4)
#define SMEM_DYN    (OFF_B1 + NLOC*4 + 256)    // ~157.8 KB

// ---------------- device globals ---------------------------------------------
__device__ __align__(128) __half g_Whh0[WELEMS];
__device__ __align__(128) __half g_Wih1[WELEMS];
__device__ __align__(128) __half g_Whh1[WELEMS];
__device__ __align__(128) __half g_h0[2][BATCH*HDIM];
__device__ __align__(128) __half g_h1[2][BATCH*HDIM];
__device__ __align__(128) float  g_h1f[BATCH*HDIM];
__device__ unsigned g_bar;

// ---------------- weight convert + barrier reset -----------------------------
__global__ void convert_kernel(const float* __restrict__ whh0,
                               const float* __restrict__ wih1,
                               const float* __restrict__ whh1) {
    long i = (long)blockIdx.x * blockDim.x + threadIdx.x;
    if (i == 0) g_bar = 0u;
    if (i < (long)WELEMS)            g_Whh0[i]             = __float2half_rn(whh0[i]);
    else if (i < 2L*WELEMS)          g_Wih1[i - WELEMS]    = __float2half_rn(wih1[i - WELEMS]);
    else if (i < 3L*WELEMS)          g_Whh1[i - 2L*WELEMS] = __float2half_rn(whh1[i - 2L*WELEMS]);
}

// ---------------- PTX helpers -------------------------------------------------
__device__ __forceinline__ void cpa16(uint32_t s, const void* g) {
    asm volatile("cp.async.cg.shared.global [%0], [%1], 16;\n" :: "r"(s), "l"(g) : "memory");
}
__device__ __forceinline__ void cp_commit() { asm volatile("cp.async.commit_group;\n" ::: "memory"); }
__device__ __forceinline__ void cp_waitp()  { asm volatile("cp.async.wait_group %0;\n" :: "n"(NSTAGE-2) : "memory"); }

__device__ __forceinline__ void ldsm_x4(uint32_t* r, uint32_t addr) {
    asm volatile("ldmatrix.sync.aligned.m8n8.x4.shared.b16 {%0,%1,%2,%3}, [%4];\n"
                 : "=r"(r[0]), "=r"(r[1]), "=r"(r[2]), "=r"(r[3]) : "r"(addr));
}
__device__ __forceinline__ void ldsm_x2(uint32_t* r, uint32_t addr) {
    asm volatile("ldmatrix.sync.aligned.m8n8.x2.shared.b16 {%0,%1}, [%2];\n"
                 : "=r"(r[0]), "=r"(r[1]) : "r"(addr));
}
__device__ __forceinline__ void mma16816(float* d, const uint32_t* a, uint32_t b0, uint32_t b1) {
    asm volatile(
        "mma.sync.aligned.m16n8k16.row.col.f32.f16.f16.f32 "
        "{%0,%1,%2,%3}, {%4,%5,%6,%7}, {%8,%9}, {%0,%1,%2,%3};\n"
        : "+f"(d[0]), "+f"(d[1]), "+f"(d[2]), "+f"(d[3])
        : "r"(a[0]), "r"(a[1]), "r"(a[2]), "r"(a[3]), "r"(b0), "r"(b1));
}

__device__ __forceinline__ float sigm(float x)  { return __fdividef(1.0f, 1.0f + __expf(-x)); }
__device__ __forceinline__ float tanh_f(float x){ return __fdividef(2.0f, 1.0f + __expf(-2.0f*x)) - 1.0f; }

// ---------------- per-thread precomputed context ------------------------------
struct Ctx {
    uint32_t offA0, offA1;   // A row-base byte offsets (tm=0,1) within a stage
    uint32_t offB4, offB2;   // B row-base byte offsets (x4 tiles, x2 tile)
    uint32_t cq4[8], cq2[8]; // per-k16 swizzled column offsets (within 256B row)
    int gid, tig, wm, wn;
};

// A: 128 rows x 16 16B-segs = 2048 segs (8/thread); B: 48 x 16 = 768 segs (3/thread)
__device__ __forceinline__ void load_stage(uint32_t sb, int buf,
                                           const __half* __restrict__ A,
                                           const __half* __restrict__ W,
                                           int j0, int k0, int tid) {
    uint32_t sbuf = sb + (uint32_t)buf * STAGE_BYTES;
#pragma unroll
    for (int it = 0; it < 8; it++) {
        int seg = tid + it*NTHREADS;
        int r = seg >> 4, s = seg & 15;
        uint32_t off = (uint32_t)(r*RB + ((s >> 3) << 7) + (((s & 7) ^ (r & 7)) << 4));
        cpa16(sbuf + off, A + (size_t)r*HDIM + k0 + s*8);
    }
#pragma unroll
    for (int it = 0; it < 3; it++) {
        int seg = tid + it*NTHREADS;
        if (seg < 768) {
            int r = seg >> 4, s = seg & 15;
            int wrow = (r / NC) * HDIM + j0 + (r % NC);
            uint32_t off = (uint32_t)(r*RB + ((s >> 3) << 7) + (((s & 7) ^ (r & 7)) << 4));
            cpa16(sbuf + A_BYTES + off, W + (size_t)wrow*HDIM + k0 + s*8);
        }
    }
}

__device__ __forceinline__ void compute_stage(uint32_t sb, int buf, const Ctx& c,
                                              float acc[2][3][4]) {
    uint32_t stage  = sb + (uint32_t)buf * STAGE_BYTES;
    uint32_t bstage = stage + A_BYTES;
#pragma unroll
    for (int q = 0; q < 8; q++) {
        uint32_t ra[2][4], rb[4], rb2[2];
        ldsm_x4(ra[0], stage + c.offA0 + c.cq4[q]);
        ldsm_x4(ra[1], stage + c.offA1 + c.cq4[q]);
        ldsm_x4(rb,    bstage + c.offB4 + c.cq4[q]);
        ldsm_x2(rb2,   bstage + c.offB2 + c.cq2[q]);
#pragma unroll
        for (int tm = 0; tm < 2; tm++) {
            mma16816(acc[tm][0], ra[tm], rb[0],  rb[2]);
            mma16816(acc[tm][1], ra[tm], rb[1],  rb[3]);
            mma16816(acc[tm][2], ra[tm], rb2[0], rb2[1]);
        }
    }
}

// multistage pipelined GEMM over npair K-concatenated (A,W) pairs
__device__ __forceinline__ void gemm_multi(uint32_t sb, const Ctx& c, int j0, int tid,
                                           const __half* A0, const __half* W0,
                                           const __half* A1, const __half* W1,
                                           int npair, float acc[2][3][4]) {
    const int total = npair * NCHUNK;
#pragma unroll
    for (int s = 0; s < NSTAGE-1; s++) {
        const __half* A = (s < NCHUNK) ? A0 : A1;
        const __half* W = (s < NCHUNK) ? W0 : W1;
        load_stage(sb, s % NSTAGE, A, W, j0, (s % NCHUNK)*KC, tid);
        cp_commit();
    }
#pragma unroll 1
    for (int s = 0; s < total; s++) {
        cp_waitp();
        __syncthreads();
        int ns = s + NSTAGE - 1;
        if (ns < total) {
            const __half* A = (ns < NCHUNK) ? A0 : A1;
            const __half* W = (ns < NCHUNK) ? W0 : W1;
            load_stage(sb, ns % NSTAGE, A, W, j0, (ns % NCHUNK)*KC, tid);
        }
        cp_commit();
        compute_stage(sb, s % NSTAGE, c, acc);
    }
}

__device__ __forceinline__ void store_gates(float* sG, const Ctx& c,
                                            const float acc[2][3][4]) {
#pragma unroll
    for (int tm = 0; tm < 2; tm++)
#pragma unroll
        for (int tn = 0; tn < 3; tn++) {
            int row = c.wm*32 + tm*16 + c.gid;
            int n   = c.wn*24 + tn*8 + c.tig*2;
            float* p0 = sG + row*NLOC + n;
            p0[0] = acc[tm][tn][0]; p0[1] = acc[tm][tn][1];
            float* p1 = sG + (row + 8)*NLOC + n;
            p1[0] = acc[tm][tn][2]; p1[1] = acc[tm][tn][3];
        }
}

__device__ __forceinline__ void gridbar(unsigned target) {
    __threadfence();
    __syncthreads();
    if (threadIdx.x == 0) {
        atomicAdd(&g_bar, 1u);
        while (*((volatile unsigned*)&g_bar) < target) { __nanosleep(32); }
    }
    __syncthreads();
}

// ---------------- persistent LSTM kernel -------------------------------------
__global__ void __launch_bounds__(NTHREADS, 1)
lstm_kernel(const float* __restrict__ x,
            const float* __restrict__ Wih0,
            const float* __restrict__ bih0, const float* __restrict__ bhh0,
            const float* __restrict__ bih1, const float* __restrict__ bhh1,
            const float* __restrict__ Wlin, const float* __restrict__ blin,
            float* __restrict__ out) {
    extern __shared__ unsigned char dsm[];
    const int tid = threadIdx.x;
    const int j0  = blockIdx.x * NC;
    const uint32_t sb = (uint32_t)__cvta_generic_to_shared(dsm);
    float* sG  = (float*)(dsm + OFF_GATES);
    float* sWx = (float*)(dsm + OFF_WX);
    float* sB0 = (float*)(dsm + OFF_B0);
    float* sB1 = (float*)(dsm + OFF_B1);

    // ---- per-thread fragment addressing context ----
    Ctx c;
    {
        int lane = tid & 31, warp = tid >> 5;
        c.gid = lane >> 2; c.tig = lane & 3;
        c.wm = warp & 3;   c.wn = warp >> 2;
        int r16 = lane & 15, hi = lane >> 4, xv = lane & 7;
        c.offA0 = (uint32_t)((c.wm*32 + r16) * RB);
        c.offA1 = c.offA0 + 16*RB;
        c.offB4 = (uint32_t)((c.wn*24 + r16) * RB);
        c.offB2 = (uint32_t)((c.wn*24 + 16 + (lane & 7)) * RB);
        int hi2 = (lane >> 3) & 1;
#pragma unroll
        for (int q = 0; q < 8; q++) {
            int u4 = 2*q + hi;
            int u2 = 2*q + hi2;
            c.cq4[q] = (uint32_t)(((u4 >> 3) << 7) + (((u4 & 7) ^ xv) << 4));
            c.cq2[q] = (uint32_t)(((u2 >> 3) << 7) + (((u2 & 7) ^ xv) << 4));
        }
    }

    // ---- constants: x-projection slice + fused biases ----
    for (int n = tid; n < NLOC; n += NTHREADS) {
        int grow = (n / NC) * HDIM + j0 + (n % NC);
        sB0[n] = bih0[grow] + bhh0[grow];
        sB1[n] = bih1[grow] + bhh1[grow];
#pragma unroll
        for (int k = 0; k < INDIM; k++) sWx[n*INDIM + k] = Wih0[grow*INDIM + k];
    }

    // ---- zero initial h state (each CTA owns its slice) ----
    for (int e = tid; e < BATCH*NC; e += NTHREADS) {
        int b = e / NC, j = e % NC;
        int idx = b*HDIM + j0 + j;
        g_h0[0][idx] = __float2half_rn(0.0f);
        g_h1[0][idx] = __float2half_rn(0.0f);
    }

    // c-state in registers: thread owns elements e = tid + i*256, i<6
    float cr0[6], cr1[6];
#pragma unroll
    for (int i = 0; i < 6; i++) { cr0[i] = 0.0f; cr1[i] = 0.0f; }

    unsigned bc = 0;
    gridbar(++bc * NCTA);

#pragma unroll 1
    for (int t = 0; t < T_STEPS; t++) {
        const int p = t & 1;

        // ================= layer 0: gates = Whh0 * h0[p] =================
        float acc[2][3][4];
#pragma unroll
        for (int a = 0; a < 2; a++)
#pragma unroll
            for (int b = 0; b < 3; b++)
#pragma unroll
                for (int d = 0; d < 4; d++) acc[a][b][d] = 0.0f;

        gemm_multi(sb, c, j0, tid, g_h0[p], g_Whh0, g_h0[p], g_Whh0, 1, acc);
        store_gates(sG, c, acc);
        __syncthreads();

        {
            const float* xt = x + (size_t)t * BATCH * INDIM;
#pragma unroll
            for (int i = 0; i < 6; i++) {
                int e = tid + i*NTHREADS;
                int b = e / NC, j = e % NC;
                float iv = sG[b*NLOC + j]          + sB0[j];
                float fv = sG[b*NLOC + NC + j]     + sB0[NC + j];
                float gv = sG[b*NLOC + 2*NC + j]   + sB0[2*NC + j];
                float ov = sG[b*NLOC + 3*NC + j]   + sB0[3*NC + j];
                const float* xr = xt + b*INDIM;
#pragma unroll
                for (int k = 0; k < INDIM; k++) {
                    float xk = xr[k];
                    iv += xk * sWx[j*INDIM + k];
                    fv += xk * sWx[(NC + j)*INDIM + k];
                    gv += xk * sWx[(2*NC + j)*INDIM + k];
                    ov += xk * sWx[(3*NC + j)*INDIM + k];
                }
                float cn = sigm(fv)*cr0[i] + sigm(iv)*tanh_f(gv);
                cr0[i] = cn;
                g_h0[p ^ 1][(size_t)b*HDIM + j0 + j] = __float2half_rn(sigm(ov)*tanh_f(cn));
            }
        }
        gridbar(++bc * NCTA);     // h0[p^1] visible chip-wide

        // ===== layer 1: gates = Wih1*h0[p^1] + Whh1*h1[p] (fused K=3072) =====
#pragma unroll
        for (int a = 0; a < 2; a++)
#pragma unroll
            for (int b = 0; b < 3; b++)
#pragma unroll
                for (int d = 0; d < 4; d++) acc[a][b][d] = 0.0f;

        gemm_multi(sb, c, j0, tid, g_h0[p ^ 1], g_Wih1, g_h1[p], g_Whh1, 2, acc);
        store_gates(sG, c, acc);
        __syncthreads();

        {
            const bool last = (t == T_STEPS - 1);
#pragma unroll
            for (int i = 0; i < 6; i++) {
                int e = tid + i*NTHREADS;
                int b = e / NC, j = e % NC;
                float iv = sG[b*NLOC + j]          + sB1[j];
                float fv = sG[b*NLOC + NC + j]     + sB1[NC + j];
                float gv = sG[b*NLOC + 2*NC + j]   + sB1[2*NC + j];
                float ov = sG[b*NLOC + 3*NC + j]   + sB1[3*NC + j];
                float cn = sigm(fv)*cr1[i] + sigm(iv)*tanh_f(gv);
                cr1[i] = cn;
                float hn = sigm(ov)*tanh_f(cn);
                g_h1[p ^ 1][(size_t)b*HDIM + j0 + j] = __float2half_rn(hn);
                if (last) g_h1f[(size_t)b*HDIM + j0 + j] = hn;
            }
        }
        gridbar(++bc * NCTA);     // h1[p^1] visible chip-wide
    }

    // ================= final linear (CTA 0) =================
    if (blockIdx.x == 0) {
#pragma unroll 1
        for (int e = tid; e < BATCH*OUTDIM; e += NTHREADS) {
            int b = e / OUTDIM, o = e % OUTDIM;
            float s = blin[o];
            const float* hr = g_h1f + (size_t)b*HDIM;
            const float* wr = Wlin + (size_t)o*HDIM;
#pragma unroll 4
            for (int k = 0; k < HDIM; k++) s += hr[k] * wr[k];
            out[b*OUTDIM + o] = s;
        }
    }
}

// ---------------- launch ------------------------------------------------------
extern "C" void kernel_launch(void* const* d_in, const int* in_sizes, int n_in,
                              void* d_out, int out_size) {
    const float* x    = (const float*)d_in[0];
    const float* Wih0 = (const float*)d_in[1];
    const float* Whh0 = (const float*)d_in[2];
    const float* bih0 = (const float*)d_in[3];
    const float* bhh0 = (const float*)d_in[4];
    const float* Wih1 = (const float*)d_in[5];
    const float* Whh1 = (const float*)d_in[6];
    const float* bih1 = (const float*)d_in[7];
    const float* bhh1 = (const float*)d_in[8];
    const float* Wlin = (const float*)d_in[9];
    const float* blin = (const float*)d_in[10];

    cudaFuncSetAttribute(lstm_kernel, cudaFuncAttributeMaxDynamicSharedMemorySize, SMEM_DYN);

    int cblocks = (3*WELEMS + 255) / 256;
    convert_kernel<<<cblocks, 256>>>(Whh0, Wih1, Whh1);
    lstm_kernel<<<NCTA, NTHREADS, SMEM_DYN>>>(x, Wih0, bih0, bhh0, bih1, bhh1,
                                              Wlin, blin, (float*)d_out);
}